// round 3
// baseline (speedup 1.0000x reference)
#include <cuda_runtime.h>

// CapsuleLayer dynamic routing, factored (u_hat never materialized), f32x2 packed math.
// X[B=128, I=1152, J=128], W[J=128, K=32, D=32], out V[B=128, K=32, D=32]
//
//   c[i,k]  = softmax_k(bl[k,i])              (it0: uniform 1/32 -> column sum)
//   y[k,j]  = sum_i c[i,k] x[i,j]             GEMM1
//   s[k,d]  = sum_j y[k,j] W[j,k,d]
//   v       = squash(s)
//   T[k,j]  = sum_d v[k,d] W[j,k,d]
//   bl[k,i] += sum_j x[i,j] T[k,j]            GEMM2 (skip last iter)

#define BB 128
#define II 1152
#define JJ 128
#define KK 32
#define DD 32
#define KD 1024
#define CI 128
#define XPF 132          // xs pitch (floats): %4==0 for float4, 4*lane bank pattern conflict-free
#define C2P 68           // c2 pitch (floats)
#define NCHUNK 9
#define NT 512

typedef unsigned long long u64;

#define FMA2(d,a,b,c) asm("fma.rn.f32x2 %0, %1, %2, %3;" : "=l"(d) : "l"(a), "l"(b), "l"(c))
#define ADD2(d,a,b)   asm("add.rn.f32x2 %0, %1, %2;" : "=l"(d) : "l"(a), "l"(b))
#define MUL2(d,a,b)   asm("mul.rn.f32x2 %0, %1, %2;" : "=l"(d) : "l"(a), "l"(b))

// routing logits scratch [b][k][i]
__device__ float g_bl[(size_t)BB * KK * II];

// smem float offsets
#define SM_XS 0          // 128*132          = 16896  (also 16x 32x33 W-transpose scratch)
#define SM_C2 16896      // 128*68           = 8704   (softmax, each c duplicated in pairs)
#define SM_YP 25600      // 4*4096           = 16384  (y partials / y / bl partials / colsum scratch)
#define SM_T  41984      // 32*128           = 4096
#define SM_SV 46080      // 1024
#define SM_SC 47104      // 32
#define SM_CS 47136      // 128
#define SM_FLOATS 47264
#define SMEM_BYTES (SM_FLOATS * 4)

__global__ __launch_bounds__(NT, 1)
void caps_routing_kernel(const float* __restrict__ X,
                         const float* __restrict__ W,
                         float* __restrict__ out)
{
    extern __shared__ float sm[];
    float* xs  = sm + SM_XS;
    float* c2  = sm + SM_C2;
    float* yp  = sm + SM_YP;
    float* Tm  = sm + SM_T;
    float* sv  = sm + SM_SV;
    float* scl = sm + SM_SC;
    float* cs  = sm + SM_CS;

    const int b    = blockIdx.x;
    const int t    = threadIdx.x;
    const int lane = t & 31;
    const int w    = t >> 5;     // 16 warps

    const float* __restrict__ xg = X + (size_t)b * (II * JJ);
    float* __restrict__ blg = g_bl + (size_t)b * (KK * II);

    for (int it = 0; it < 3; ++it) {
        // ================= y[k][j] =================
        if (it == 0) {
            // y[k][j] = (1/32) sum_i x[i][j], identical for every k
            const int part = w, jq = lane;          // 16 i-partitions x 32 float4 cols
            u64 s0 = 0, s1 = 0;
            const float* xp = xg + (size_t)(part * 72) * JJ + jq * 4;
            #pragma unroll 4
            for (int ii = 0; ii < 72; ++ii) {
                ulonglong2 v = *(const ulonglong2*)(xp + (size_t)ii * JJ);
                ADD2(s0, s0, v.x); ADD2(s1, s1, v.y);
            }
            ((ulonglong2*)yp)[part * 32 + jq] = make_ulonglong2(s0, s1);
            __syncthreads();
            if (t < 32) {
                u64 a0 = 0, a1 = 0;
                #pragma unroll
                for (int p = 0; p < 16; ++p) {
                    ulonglong2 v = ((ulonglong2*)yp)[p * 32 + t];
                    ADD2(a0, a0, v.x); ADD2(a1, a1, v.y);
                }
                const unsigned int ui = __float_as_uint(1.0f / 32.0f);
                const u64 sc2 = (u64)ui | ((u64)ui << 32);
                MUL2(a0, a0, sc2); MUL2(a1, a1, sc2);
                ((ulonglong2*)cs)[t] = make_ulonglong2(a0, a1);
            }
            __syncthreads();
            #pragma unroll
            for (int pp = 0; pp < 2; ++pp) {
                const int e4 = t + pp * NT;                       // e4 = k*32 + j4
                ((ulonglong2*)yp)[e4] = ((const ulonglong2*)cs)[e4 & 31];
            }
            __syncthreads();
        } else {
            // GEMM1: warp = (kg: 8 k's) x (full 128 j via float4/lane) x (is: 32 i per chunk)
            const int kg = w & 3, is = w >> 2;
            u64 acc[8][2];
            #pragma unroll
            for (int q = 0; q < 8; ++q) { acc[q][0] = 0; acc[q][1] = 0; }

            for (int ch = 0; ch < NCHUNK; ++ch) {
                const int ibase = ch * CI;
                __syncthreads();                     // xs / c2 reusable
                // stage x chunk (float4, coalesced, conflict-free)
                #pragma unroll
                for (int ee = 0; ee < 8; ++ee) {
                    const int e4 = t + ee * NT;
                    const int il = e4 >> 5, j4 = e4 & 31;
                    ulonglong2 v = *(const ulonglong2*)(xg + (size_t)(ibase + il) * JJ + j4 * 4);
                    *(ulonglong2*)(xs + il * XPF + j4 * 4) = v;
                }
                // softmax over k; write c duplicated-in-pairs for f32x2 consumption
                if (t < CI) {
                    const int i = ibase + t;
                    float vv[KK]; float mx = -1e30f;
                    #pragma unroll
                    for (int k = 0; k < KK; ++k) { vv[k] = blg[k * II + i]; mx = fmaxf(mx, vv[k]); }
                    float ssum = 0.f;
                    #pragma unroll
                    for (int k = 0; k < KK; ++k) { vv[k] = __expf(vv[k] - mx); ssum += vv[k]; }
                    const float inv = 1.0f / ssum;
                    float4* c2r = (float4*)(c2 + t * C2P);
                    #pragma unroll
                    for (int kq = 0; kq < 16; ++kq) {
                        const float a = vv[2 * kq] * inv, bq = vv[2 * kq + 1] * inv;
                        c2r[kq] = make_float4(a, a, bq, bq);
                    }
                }
                __syncthreads();
                // compute: per i -> 5 LDS.128 + 16 FFMA2
                #pragma unroll 4
                for (int ii = 0; ii < 32; ++ii) {
                    const int i = is * 32 + ii;
                    ulonglong2 xv = *(const ulonglong2*)(xs + i * XPF + lane * 4);
                    const ulonglong2* cr = (const ulonglong2*)(c2 + i * C2P + kg * 16);
                    #pragma unroll
                    for (int q = 0; q < 4; ++q) {
                        ulonglong2 cq = cr[q];
                        FMA2(acc[2*q  ][0], cq.x, xv.x, acc[2*q  ][0]);
                        FMA2(acc[2*q  ][1], cq.x, xv.y, acc[2*q  ][1]);
                        FMA2(acc[2*q+1][0], cq.y, xv.x, acc[2*q+1][0]);
                        FMA2(acc[2*q+1][1], cq.y, xv.y, acc[2*q+1][1]);
                    }
                }
            }
            __syncthreads();
            #pragma unroll
            for (int q = 0; q < 8; ++q) {
                const int k = kg * 8 + q;
                *(ulonglong2*)(yp + is * 4096 + k * JJ + lane * 4) =
                    make_ulonglong2(acc[q][0], acc[q][1]);
            }
            __syncthreads();
            // reduce 4 i-split partials into yp[0]
            #pragma unroll
            for (int pp = 0; pp < 2; ++pp) {
                const int e4 = t + pp * NT;
                ulonglong2 a = ((ulonglong2*)yp)[e4];
                #pragma unroll
                for (int p = 1; p < 4; ++p) {
                    ulonglong2 v = ((ulonglong2*)yp)[p * 1024 + e4];
                    ADD2(a.x, a.x, v.x); ADD2(a.y, a.y, v.y);
                }
                ((ulonglong2*)yp)[e4] = a;
            }
            __syncthreads();
        }

        // ================= s[k][d] = sum_j y[k][j] W[j,k,d] =================
        #pragma unroll
        for (int pp = 0; pp < 2; ++pp) {
            const int p = t + pp * NT;
            const int k = p >> 5, d = p & 31;
            const float* Wp = W + k * DD + d;       // coalesced over d (lanes)
            const float* yk = yp + k * JJ;          // broadcast
            float acc = 0.f;
            #pragma unroll 8
            for (int j = 0; j < JJ; ++j)
                acc = fmaf(yk[j], Wp[(size_t)j * KD], acc);
            sv[p] = acc;
        }
        __syncthreads();

        // ================= squash =================
        if (t < KK) {
            float ss = 0.f;
            #pragma unroll
            for (int d = 0; d < DD; ++d) { const float q = sv[t * DD + d]; ss += q * q; }
            scl[t] = ss / (1.0f + ss) * rsqrtf(ss + 1e-7f);
        }
        __syncthreads();
        #pragma unroll
        for (int pp = 0; pp < 2; ++pp) {
            const int p = t + pp * NT;
            sv[p] *= scl[p >> 5];
        }
        __syncthreads();

        if (it == 2) {
            #pragma unroll
            for (int pp = 0; pp < 2; ++pp) {
                const int p = t + pp * NT;
                out[(size_t)b * KD + p] = sv[p];
            }
            return;
        }

        // ======= T[k][j] = sum_d v[k][d] W[j,k,d], coalesced via smem transpose =======
        {
            float* wt = xs + w * 1056;               // private 32x33 tile per warp
            #pragma unroll
            for (int kk = 0; kk < 2; ++kk) {
                const int k = 2 * w + kk;
                #pragma unroll
                for (int jb = 0; jb < 4; ++jb) {
                    #pragma unroll 8
                    for (int j2 = 0; j2 < 32; ++j2)  // coalesced LDG, conflict-free STS
                        wt[lane * 33 + j2] = W[(size_t)(jb * 32 + j2) * KD + k * DD + lane];
                    __syncwarp();
                    float acc = 0.f;                 // lane = j
                    #pragma unroll
                    for (int d = 0; d < 32; ++d)
                        acc = fmaf(wt[d * 33 + lane], sv[k * DD + d], acc);
                    Tm[k * JJ + jb * 32 + lane] = acc;
                    __syncwarp();
                }
            }
        }
        __syncthreads();

        // ========== GEMM2: bl[k][i] (+)= sum_j x[i][j] T[k][j] ==========
        {
            const int kg = w & 3, ig = (w >> 2) & 1, js = w >> 3;
            const int i0 = ig * 64 + lane;
            for (int ch = 0; ch < NCHUNK; ++ch) {
                const int ibase = ch * CI;
                __syncthreads();                     // xs / yp reusable
                #pragma unroll
                for (int ee = 0; ee < 8; ++ee) {
                    const int e4 = t + ee * NT;
                    const int il = e4 >> 5, j4 = e4 & 31;
                    ulonglong2 v = *(const ulonglong2*)(xg + (size_t)(ibase + il) * JJ + j4 * 4);
                    *(ulonglong2*)(xs + il * XPF + j4 * 4) = v;
                }
                __syncthreads();
                u64 acc[8][2];
                #pragma unroll
                for (int q = 0; q < 8; ++q) { acc[q][0] = 0; acc[q][1] = 0; }
                #pragma unroll 2
                for (int st = 0; st < 16; ++st) {    // 4 j per step, 64 j per warp
                    const int jj = js * 16 + st;
                    ulonglong2 x0 = *(const ulonglong2*)(xs + i0 * XPF + jj * 4);
                    ulonglong2 x1 = *(const ulonglong2*)(xs + (i0 + 32) * XPF + jj * 4);
                    #pragma unroll
                    for (int q = 0; q < 8; ++q) {
                        const int k = kg * 8 + q;
                        ulonglong2 tq = *(const ulonglong2*)(Tm + k * JJ + jj * 4); // bcast
                        FMA2(acc[q][0], tq.x, x0.x, acc[q][0]);
                        FMA2(acc[q][0], tq.y, x0.y, acc[q][0]);
                        FMA2(acc[q][1], tq.x, x1.x, acc[q][1]);
                        FMA2(acc[q][1], tq.y, x1.y, acc[q][1]);
                    }
                }
                // partials (j-split 2) into yp
                #pragma unroll
                for (int q = 0; q < 8; ++q) {
                    const int k = kg * 8 + q;
                    float2 f0 = *(float2*)&acc[q][0];
                    float2 f1 = *(float2*)&acc[q][1];
                    yp[js * 4096 + k * JJ + ig * 64 + lane]      = f0.x + f0.y;
                    yp[js * 4096 + k * JJ + ig * 64 + 32 + lane] = f1.x + f1.y;
                }
                __syncthreads();
                // combine + global update (coalesced)
                #pragma unroll
                for (int ee = 0; ee < 8; ++ee) {
                    const int e = t + ee * NT;
                    const float val = yp[e] + yp[4096 + e];
                    const int k = e >> 7, iL = e & 127;
                    const size_t gi = (size_t)k * II + ibase + iL;
                    if (it == 0) blg[gi] = val;
                    else         blg[gi] += val;
                }
            }
        }
    }
}

extern "C" void kernel_launch(void* const* d_in, const int* in_sizes, int n_in,
                              void* d_out, int out_size)
{
    (void)in_sizes; (void)n_in; (void)out_size;
    const float* X = (const float*)d_in[0];   // [128, 1152, 128] f32
    const float* W = (const float*)d_in[1];   // [128, 32, 32] f32
    float* out = (float*)d_out;               // [128, 32, 32] f32

    cudaFuncSetAttribute(caps_routing_kernel,
                         cudaFuncAttributeMaxDynamicSharedMemorySize, SMEM_BYTES);
    caps_routing_kernel<<<BB, NT, SMEM_BYTES>>>(X, W, out);
}